// round 13
// baseline (speedup 1.0000x reference)
#include <cuda_runtime.h>
#include <cuda_fp16.h>
#include <math.h>
#include <stdint.h>

// Problem sizes (fixed)
#define B_    16
#define S_    4096
#define D2_   1024      // 2H
#define H_    512
#define M_    (B_ * S_)

// Scratch
__device__ float g_hproj[B_ * H_];
__device__ float g_partial[4 * M_];          // per-ntile partial row sums
__device__ float g_scores[M_];               // softmaxed attention
__device__ float g_ctx[8 * B_ * D2_];        // per-schunk context partials
__device__ __half g_W16[D2_ * H_];           // W bottom fp16 [k][n]
__device__ uint4  g_enc16[(size_t)M_ * D2_ / 8];   // enc fp16, row-major [M][1024]

// BK=32. smem pitches (halves)
#define PA 40     // A rows: 32 halves + 8 pad (80 B)
#define PB 136    // B rows: 128 halves + 8 pad (272 B)
#define STAGES 3
#define NKC 32
#define ASZ (128 * PA)          // 5120 halves (10240 B)
#define BSZ (32 * PB)           // 4352 halves (8704 B)
#define STAGE_BYTES ((ASZ + BSZ) * 2)        // 18944
#define SMEM_DYN (STAGES * STAGE_BYTES)      // 56832

// ---------------------------------------------------------------------------
// helpers
// ---------------------------------------------------------------------------
__device__ __forceinline__ uint32_t smem_u32(const void* p) {
    uint32_t a;
    asm("{ .reg .u64 t; cvta.to.shared.u64 t, %1; cvt.u32.u64 %0, t; }" : "=r"(a) : "l"(p));
    return a;
}
__device__ __forceinline__ void ldmx4(uint32_t addr, uint32_t& r0, uint32_t& r1,
                                      uint32_t& r2, uint32_t& r3) {
    asm volatile("ldmatrix.sync.aligned.m8n8.x4.shared.b16 {%0,%1,%2,%3}, [%4];"
                 : "=r"(r0), "=r"(r1), "=r"(r2), "=r"(r3) : "r"(addr));
}
__device__ __forceinline__ void ldmx4t(uint32_t addr, uint32_t& r0, uint32_t& r1,
                                       uint32_t& r2, uint32_t& r3) {
    asm volatile("ldmatrix.sync.aligned.m8n8.x4.trans.shared.b16 {%0,%1,%2,%3}, [%4];"
                 : "=r"(r0), "=r"(r1), "=r"(r2), "=r"(r3) : "r"(addr));
}
__device__ __forceinline__ void mma16816(float* c, uint32_t a0, uint32_t a1,
                                         uint32_t a2, uint32_t a3,
                                         uint32_t b0, uint32_t b1) {
    asm volatile(
        "mma.sync.aligned.m16n8k16.row.col.f32.f16.f16.f32 "
        "{%0,%1,%2,%3},{%4,%5,%6,%7},{%8,%9},{%0,%1,%2,%3};"
        : "+f"(c[0]), "+f"(c[1]), "+f"(c[2]), "+f"(c[3])
        : "r"(a0), "r"(a1), "r"(a2), "r"(a3), "r"(b0), "r"(b1));
}
__device__ __forceinline__ void cp16(uint32_t dst, const void* src) {
    asm volatile("cp.async.cg.shared.global [%0], [%1], 16;" :: "r"(dst), "l"(src));
}

// ---------------------------------------------------------------------------
// hproj[b][h] = b_attn[h] + hidden[b] @ W_top[:,h]
// ---------------------------------------------------------------------------
__global__ __launch_bounds__(512) void hproj_kernel(
    const float* __restrict__ hidden, const float* __restrict__ W,
    const float* __restrict__ b_attn)
{
    __shared__ float hid_s[D2_];
    int b = blockIdx.x, h = threadIdx.x;
    for (int d = threadIdx.x; d < D2_; d += blockDim.x)
        hid_s[d] = hidden[b * D2_ + d];
    __syncthreads();
    float acc = b_attn[h];
    #pragma unroll 8
    for (int d = 0; d < D2_; ++d)
        acc = fmaf(hid_s[d], W[(size_t)d * H_ + h], acc);
    g_hproj[b * H_ + h] = acc;
}

// ---------------------------------------------------------------------------
// pack W bottom [1024,512] fp32 -> fp16 [k][n]
// ---------------------------------------------------------------------------
__global__ __launch_bounds__(256) void wpack_kernel(const float* __restrict__ W) {
    int idx = blockIdx.x * 256 + threadIdx.x;
    g_W16[idx] = __float2half(W[(size_t)D2_ * H_ + idx]);
}

// ---------------------------------------------------------------------------
// pack enc [M,1024] fp32 -> fp16 (8 elems / thread)
// ---------------------------------------------------------------------------
__global__ __launch_bounds__(256) void epack_kernel(const float* __restrict__ enc) {
    size_t idx = (size_t)blockIdx.x * 256 + threadIdx.x;   // 0 .. 8M-1
    const float4* src = (const float4*)enc + idx * 2;
    float4 f0 = src[0], f1 = src[1];
    __half2 h0 = __floats2half2_rn(f0.x, f0.y);
    __half2 h1 = __floats2half2_rn(f0.z, f0.w);
    __half2 h2 = __floats2half2_rn(f1.x, f1.y);
    __half2 h3 = __floats2half2_rn(f1.z, f1.w);
    uint4 o;
    o.x = *(uint32_t*)&h0; o.y = *(uint32_t*)&h1;
    o.z = *(uint32_t*)&h2; o.w = *(uint32_t*)&h3;
    g_enc16[idx] = o;
}

// ---------------------------------------------------------------------------
// scores GEMM: C = enc16 @ W16, CTA 128x128x32, 128 threads (4 warps),
// warp tile 64x64 (LDSM/HMMA = 0.25), 3-stage cp.async, 3 CTAs/SM.
// Targets the smem-crossbar bound identified in R12 post-mortem.
// ---------------------------------------------------------------------------
__global__ __launch_bounds__(128, 3) void scores_kernel(const float* __restrict__ wv)
{
    extern __shared__ __align__(16) char dsm[];
    __shared__ float hp_s[128], wv_s[128], red[256];

    const int tid = threadIdx.x, wid = tid >> 5, lane = tid & 31;
    const int mtile = blockIdx.x >> 2;     // ntile-fastest for L2 A reuse
    const int ntile = blockIdx.x & 3;
    const int b = mtile >> 5;

    hp_s[tid] = g_hproj[b * H_ + ntile * 128 + tid];
    wv_s[tid] = wv[ntile * 128 + tid];

    const __half* Aenc = (const __half*)g_enc16 + (size_t)mtile * 128 * D2_;
    const __half* Bw   = g_W16 + ntile * 128;
    const uint32_t sm_b = smem_u32(dsm);

    // cp.async: A = 512 chunks (row = tid, 4 chunks each); B = 512 chunks, 4/thread
    const int bc0 = tid * 4;
    auto issue_stage = [&](int kc, int s) {
        uint32_t base = sm_b + (uint32_t)s * STAGE_BYTES;
        #pragma unroll
        for (int i = 0; i < 4; ++i)
            cp16(base + (uint32_t)(tid * PA * 2 + i * 16),
                 Aenc + (size_t)tid * D2_ + kc * 32 + i * 8);
        uint32_t bbase = base + ASZ * 2;
        #pragma unroll
        for (int i = 0; i < 4; ++i) {
            int c = bc0 + i;
            int row = c >> 4, cc = c & 15;
            cp16(bbase + (uint32_t)(row * PB * 2 + cc * 16),
                 Bw + (size_t)(kc * 32 + row) * H_ + cc * 8);
        }
        asm volatile("cp.async.commit_group;" ::: "memory");
    };

    // accumulators: 4 m-atoms x 8 n-atoms x 4 f32 = 128 regs
    float acc[4][8][4];
    #pragma unroll
    for (int i = 0; i < 4; ++i)
        #pragma unroll
        for (int j = 0; j < 8; ++j)
            #pragma unroll
            for (int t = 0; t < 4; ++t) acc[i][j][t] = 0.0f;

    const int m_base = (wid >> 1) * 64;    // 2 m-groups of 64
    const int n_base = (wid & 1) * 64;     // 2 n-groups of 64
    const uint32_t a_off = ((m_base + (lane & 15)) * PA + (lane >> 4) * 8) * 2;
    const uint32_t b_off = (((lane & 7) + ((lane >> 3) & 1) * 8) * PB
                            + n_base + (lane >> 4) * 8) * 2;

    issue_stage(0, 0);
    issue_stage(1, 1);

    for (int kc = 0; kc < NKC; ++kc) {
        asm volatile("cp.async.wait_group 1;" ::: "memory");
        __syncthreads();
        if (kc + 2 < NKC) issue_stage(kc + 2, (kc + 2) % STAGES);

        const uint32_t sbase = sm_b + (uint32_t)(kc % STAGES) * STAGE_BYTES;
        const uint32_t a_base = sbase + a_off;
        const uint32_t b_base = sbase + ASZ * 2 + b_off;
        #pragma unroll
        for (int ks = 0; ks < 2; ++ks) {
            uint32_t Af[4][4], Bf[4][4];
            #pragma unroll
            for (int ma = 0; ma < 4; ++ma)
                ldmx4(a_base + (ma * 16 * PA + ks * 16) * 2,
                      Af[ma][0], Af[ma][1], Af[ma][2], Af[ma][3]);
            #pragma unroll
            for (int g = 0; g < 4; ++g)
                ldmx4t(b_base + (ks * 16 * PB + g * 16) * 2,
                       Bf[g][0], Bf[g][1], Bf[g][2], Bf[g][3]);
            #pragma unroll
            for (int ma = 0; ma < 4; ++ma)
                #pragma unroll
                for (int j = 0; j < 8; ++j)
                    mma16816(acc[ma][j], Af[ma][0], Af[ma][1], Af[ma][2], Af[ma][3],
                             Bf[j >> 1][(j & 1) * 2], Bf[j >> 1][(j & 1) * 2 + 1]);
        }
        // stage reuse ordered by the next iteration's __syncthreads.
    }

    // ---- epilogue (validated mapping, 4 m-atoms) ----
    #pragma unroll
    for (int ma = 0; ma < 4; ++ma) {
        float rs0 = 0.0f, rs1 = 0.0f;
        #pragma unroll
        for (int j = 0; j < 8; ++j) {
            int col = n_base + j * 8 + (lane & 3) * 2;
            float h0 = hp_s[col], h1 = hp_s[col + 1];
            float w0 = wv_s[col], w1 = wv_s[col + 1];
            rs0 = fmaf(tanhf(acc[ma][j][0] + h0), w0, rs0);
            rs0 = fmaf(tanhf(acc[ma][j][1] + h1), w1, rs0);
            rs1 = fmaf(tanhf(acc[ma][j][2] + h0), w0, rs1);
            rs1 = fmaf(tanhf(acc[ma][j][3] + h1), w1, rs1);
        }
        #pragma unroll
        for (int off = 1; off <= 2; off <<= 1) {
            rs0 += __shfl_xor_sync(0xffffffffu, rs0, off);
            rs1 += __shfl_xor_sync(0xffffffffu, rs1, off);
        }
        if ((lane & 3) == 0) {
            int r0 = m_base + ma * 16 + (lane >> 2);
            red[r0 * 2 + (wid & 1)] = rs0;
            red[(r0 + 8) * 2 + (wid & 1)] = rs1;
        }
    }
    __syncthreads();
    g_partial[(size_t)ntile * M_ + mtile * 128 + tid] = red[tid * 2] + red[tid * 2 + 1];
}

// ---------------------------------------------------------------------------
// softmax: fold 4 n-tile partials, softmax over S, write g_scores. grid=B_.
// ---------------------------------------------------------------------------
__global__ __launch_bounds__(512) void softmax_kernel() {
    __shared__ float sc_s[S_];
    __shared__ float red2[512];
    const int b = blockIdx.x, tid = threadIdx.x;

    float lmax = -1e30f;
    for (int s = tid; s < S_; s += 512) {
        size_t m = (size_t)b * S_ + s;
        float v = g_partial[m] + g_partial[M_ + m] +
                  g_partial[2 * (size_t)M_ + m] + g_partial[3 * (size_t)M_ + m];
        sc_s[s] = v;
        lmax = fmaxf(lmax, v);
    }
    red2[tid] = lmax; __syncthreads();
    for (int off = 256; off >= 1; off >>= 1) {
        if (tid < off) red2[tid] = fmaxf(red2[tid], red2[tid + off]);
        __syncthreads();
    }
    const float mx = red2[0];
    __syncthreads();
    float lsum = 0.0f;
    for (int s = tid; s < S_; s += 512) {
        float e = __expf(sc_s[s] - mx);
        sc_s[s] = e;
        lsum += e;
    }
    red2[tid] = lsum; __syncthreads();
    for (int off = 256; off >= 1; off >>= 1) {
        if (tid < off) red2[tid] += red2[tid + off];
        __syncthreads();
    }
    const float inv = 1.0f / red2[0];
    __syncthreads();
    for (int s = tid; s < S_; s += 512)
        g_scores[b * S_ + s] = sc_s[s] * inv;
}

// ---------------------------------------------------------------------------
// context partials from fp16 enc: grid (B_, 8 dcols, 8 schunks), 256 threads.
// ---------------------------------------------------------------------------
__global__ __launch_bounds__(256) void context_kernel()
{
    __shared__ float attn_s[512];
    __shared__ float redc[8][128];

    const int b = blockIdx.x, dc = blockIdx.y, sc = blockIdx.z, tid = threadIdx.x;
    const int s0 = sc * 512;

    for (int s = tid; s < 512; s += 256)
        attn_s[s] = g_scores[b * S_ + s0 + s];
    __syncthreads();

    const int tsub = tid >> 5, lane = tid & 31;
    const __half* base = (const __half*)g_enc16
                       + ((size_t)b * S_ + s0) * D2_ + dc * 128 + lane * 4;
    float4 acc = make_float4(0.f, 0.f, 0.f, 0.f);
    #pragma unroll 8
    for (int s = tsub; s < 512; s += 8) {
        float a = attn_s[s];
        uint2 raw = *(const uint2*)(base + (size_t)s * D2_);
        float2 e0 = __half22float2(*(__half2*)&raw.x);
        float2 e1 = __half22float2(*(__half2*)&raw.y);
        acc.x = fmaf(a, e0.x, acc.x);
        acc.y = fmaf(a, e0.y, acc.y);
        acc.z = fmaf(a, e1.x, acc.z);
        acc.w = fmaf(a, e1.y, acc.w);
    }
    *(float4*)&redc[tsub][lane * 4] = acc;
    __syncthreads();
    if (tid < 128) {
        float s = 0.0f;
        #pragma unroll
        for (int t = 0; t < 8; ++t) s += redc[t][tid];
        g_ctx[((size_t)sc * B_ + b) * D2_ + dc * 128 + tid] = s;
    }
}

// ---------------------------------------------------------------------------
// reduce 8 context partials -> out
// ---------------------------------------------------------------------------
__global__ __launch_bounds__(256) void ctx_reduce_kernel(float* __restrict__ out) {
    int i = blockIdx.x * 256 + threadIdx.x;
    float s = 0.0f;
    #pragma unroll
    for (int p = 0; p < 8; ++p) s += g_ctx[(size_t)p * B_ * D2_ + i];
    out[i] = s;
}

// ---------------------------------------------------------------------------
// Launch
// ---------------------------------------------------------------------------
extern "C" void kernel_launch(void* const* d_in, const int* in_sizes, int n_in,
                              void* d_out, int out_size) {
    const float* hidden = (const float*)d_in[0];
    const float* enc    = (const float*)d_in[1];
    const float* W      = (const float*)d_in[2];
    const float* b_attn = (const float*)d_in[3];
    const float* wv     = (const float*)d_in[4];
    float* out = (float*)d_out;

    static int smem_set = 0;
    if (!smem_set) {
        cudaFuncSetAttribute(scores_kernel,
                             cudaFuncAttributeMaxDynamicSharedMemorySize, SMEM_DYN);
        smem_set = 1;
    }

    hproj_kernel<<<B_, 512>>>(hidden, W, b_attn);
    wpack_kernel<<<(D2_ * H_) / 256, 256>>>(W);
    epack_kernel<<<(unsigned)(((size_t)M_ * D2_ / 8) / 256), 256>>>(enc);
    scores_kernel<<<(M_ / 128) * 4, 128, SMEM_DYN>>>(wv);
    softmax_kernel<<<B_, 512>>>();
    context_kernel<<<dim3(B_, 8, 8), 256>>>();
    ctx_reduce_kernel<<<(B_ * D2_) / 256, 256>>>(out);
}

// round 14
// speedup vs baseline: 1.0715x; 1.0715x over previous
#include <cuda_runtime.h>
#include <cuda_fp16.h>
#include <math.h>
#include <stdint.h>

// Problem sizes (fixed)
#define B_    16
#define S_    4096
#define D2_   1024      // 2H
#define H_    512
#define M_    (B_ * S_)

// Scratch
__device__ float g_hproj[B_ * H_];
__device__ float g_partial[4 * M_];          // per-ntile partial row sums
__device__ float g_scores[M_];               // softmaxed attention
__device__ float g_ctx[8 * B_ * D2_];        // per-schunk context partials
__device__ __half g_W16[D2_ * H_];           // W bottom fp16 [k][n]
__device__ uint4  g_enc16[(size_t)M_ * D2_ / 8];   // enc fp16, row-major [M][1024]

// smem pitches (halves) — R9 configuration
#define PA 40     // A rows: 32 halves + 8 pad (80 B)
#define PB 136    // B rows: 128 halves + 8 pad (272 B)
#define STAGES 4
#define ASZ (128 * PA)          // 5120 halves
#define BSZ (32 * PB)           // 4352 halves
#define STAGE_BYTES ((ASZ + BSZ) * 2)        // 18944
#define SMEM_DYN (STAGES * STAGE_BYTES)      // 75776

// ---------------------------------------------------------------------------
// helpers
// ---------------------------------------------------------------------------
__device__ __forceinline__ uint32_t smem_u32(const void* p) {
    uint32_t a;
    asm("{ .reg .u64 t; cvta.to.shared.u64 t, %1; cvt.u32.u64 %0, t; }" : "=r"(a) : "l"(p));
    return a;
}
__device__ __forceinline__ void ldmx4(uint32_t addr, uint32_t& r0, uint32_t& r1,
                                      uint32_t& r2, uint32_t& r3) {
    asm volatile("ldmatrix.sync.aligned.m8n8.x4.shared.b16 {%0,%1,%2,%3}, [%4];"
                 : "=r"(r0), "=r"(r1), "=r"(r2), "=r"(r3) : "r"(addr));
}
__device__ __forceinline__ void ldmx4t(uint32_t addr, uint32_t& r0, uint32_t& r1,
                                       uint32_t& r2, uint32_t& r3) {
    asm volatile("ldmatrix.sync.aligned.m8n8.x4.trans.shared.b16 {%0,%1,%2,%3}, [%4];"
                 : "=r"(r0), "=r"(r1), "=r"(r2), "=r"(r3) : "r"(addr));
}
__device__ __forceinline__ void mma16816(float* c, uint32_t a0, uint32_t a1,
                                         uint32_t a2, uint32_t a3,
                                         uint32_t b0, uint32_t b1) {
    asm volatile(
        "mma.sync.aligned.m16n8k16.row.col.f32.f16.f16.f32 "
        "{%0,%1,%2,%3},{%4,%5,%6,%7},{%8,%9},{%0,%1,%2,%3};"
        : "+f"(c[0]), "+f"(c[1]), "+f"(c[2]), "+f"(c[3])
        : "r"(a0), "r"(a1), "r"(a2), "r"(a3), "r"(b0), "r"(b1));
}
__device__ __forceinline__ void cp16(uint32_t dst, const void* src) {
    asm volatile("cp.async.cg.shared.global [%0], [%1], 16;" :: "r"(dst), "l"(src));
}

// ---------------------------------------------------------------------------
// hproj[b][h] = b_attn[h] + hidden[b] @ W_top[:,h]
// ---------------------------------------------------------------------------
__global__ __launch_bounds__(512) void hproj_kernel(
    const float* __restrict__ hidden, const float* __restrict__ W,
    const float* __restrict__ b_attn)
{
    __shared__ float hid_s[D2_];
    int b = blockIdx.x, h = threadIdx.x;
    for (int d = threadIdx.x; d < D2_; d += blockDim.x)
        hid_s[d] = hidden[b * D2_ + d];
    __syncthreads();
    float acc = b_attn[h];
    #pragma unroll 8
    for (int d = 0; d < D2_; ++d)
        acc = fmaf(hid_s[d], W[(size_t)d * H_ + h], acc);
    g_hproj[b * H_ + h] = acc;
}

// ---------------------------------------------------------------------------
// pack W bottom [1024,512] fp32 -> fp16 [k][n]
// ---------------------------------------------------------------------------
__global__ __launch_bounds__(256) void wpack_kernel(const float* __restrict__ W) {
    int idx = blockIdx.x * 256 + threadIdx.x;
    g_W16[idx] = __float2half(W[(size_t)D2_ * H_ + idx]);
}

// ---------------------------------------------------------------------------
// pack enc [M,1024] fp32 -> fp16: 32 elems (4 uint4 out) per thread.
// ---------------------------------------------------------------------------
__global__ __launch_bounds__(256) void epack_kernel(const float* __restrict__ enc) {
    size_t idx = ((size_t)blockIdx.x * 256 + threadIdx.x) * 4;   // uint4 index
    const float4* src = (const float4*)enc + idx * 2;
    float4 f[8];
    #pragma unroll
    for (int i = 0; i < 8; ++i) f[i] = src[i];
    #pragma unroll
    for (int o = 0; o < 4; ++o) {
        __half2 h0 = __floats2half2_rn(f[o*2].x,   f[o*2].y);
        __half2 h1 = __floats2half2_rn(f[o*2].z,   f[o*2].w);
        __half2 h2 = __floats2half2_rn(f[o*2+1].x, f[o*2+1].y);
        __half2 h3 = __floats2half2_rn(f[o*2+1].z, f[o*2+1].w);
        uint4 v;
        v.x = *(uint32_t*)&h0; v.y = *(uint32_t*)&h1;
        v.z = *(uint32_t*)&h2; v.w = *(uint32_t*)&h3;
        g_enc16[idx + o] = v;
    }
}

// ---------------------------------------------------------------------------
// scores GEMM — exact R9 winner: CTA 128x128x32, 4-stage cp.async, 2 CTAs/SM.
// ---------------------------------------------------------------------------
__global__ __launch_bounds__(256, 2) void scores_kernel(const float* __restrict__ wv)
{
    extern __shared__ __align__(16) char dsm[];
    __shared__ float hp_s[128], wv_s[128], red[256];

    const int tid = threadIdx.x, wid = tid >> 5, lane = tid & 31;
    const int mtile = blockIdx.x >> 2;     // ntile-fastest for L2 A reuse
    const int ntile = blockIdx.x & 3;
    const int b = mtile >> 5;

    if (tid < 128) {
        hp_s[tid] = g_hproj[b * H_ + ntile * 128 + tid];
        wv_s[tid] = wv[ntile * 128 + tid];
    }

    const __half* Aenc = (const __half*)g_enc16 + (size_t)mtile * 128 * D2_;
    const __half* Bw   = g_W16 + ntile * 128;
    const uint32_t sm_b = smem_u32(dsm);

    const int ac0 = tid * 2;
    auto issue_stage = [&](int kc, int s) {
        uint32_t base = sm_b + (uint32_t)s * STAGE_BYTES;
        #pragma unroll
        for (int i = 0; i < 2; ++i) {
            int c = ac0 + i;
            int row = c >> 2, cc = c & 3;
            cp16(base + (uint32_t)(row * PA * 2 + cc * 16),
                 Aenc + (size_t)row * D2_ + kc * 32 + cc * 8);
        }
        uint32_t bbase = base + ASZ * 2;
        #pragma unroll
        for (int i = 0; i < 2; ++i) {
            int c = ac0 + i;
            int row = c >> 4, cc = c & 15;
            cp16(bbase + (uint32_t)(row * PB * 2 + cc * 16),
                 Bw + (size_t)(kc * 32 + row) * H_ + cc * 8);
        }
        asm volatile("cp.async.commit_group;" ::: "memory");
    };

    float acc[2][8][4];
    #pragma unroll
    for (int i = 0; i < 2; ++i)
        #pragma unroll
        for (int j = 0; j < 8; ++j)
            #pragma unroll
            for (int t = 0; t < 4; ++t) acc[i][j][t] = 0.0f;

    const int m_base = (wid >> 1) * 32;
    const int n_base = (wid & 1) * 64;
    const uint32_t a_off = ((m_base + (lane & 15)) * PA + (lane >> 4) * 8) * 2;
    const uint32_t b_off = (((lane & 7) + ((lane >> 3) & 1) * 8) * PB
                            + n_base + (lane >> 4) * 8) * 2;

    issue_stage(0, 0);
    issue_stage(1, 1);
    issue_stage(2, 2);

    for (int kc = 0; kc < 32; ++kc) {
        asm volatile("cp.async.wait_group 2;" ::: "memory");
        __syncthreads();
        if (kc + 3 < 32) issue_stage(kc + 3, (kc + 3) & (STAGES - 1));

        const uint32_t sbase = sm_b + (uint32_t)(kc & (STAGES - 1)) * STAGE_BYTES;
        const uint32_t a_base = sbase + a_off;
        const uint32_t b_base = sbase + ASZ * 2 + b_off;
        #pragma unroll
        for (int ks = 0; ks < 2; ++ks) {
            uint32_t Af[2][4], Bf[4][4];
            #pragma unroll
            for (int ma = 0; ma < 2; ++ma)
                ldmx4(a_base + (ma * 16 * PA + ks * 16) * 2,
                      Af[ma][0], Af[ma][1], Af[ma][2], Af[ma][3]);
            #pragma unroll
            for (int g = 0; g < 4; ++g)
                ldmx4t(b_base + (ks * 16 * PB + g * 16) * 2,
                       Bf[g][0], Bf[g][1], Bf[g][2], Bf[g][3]);
            #pragma unroll
            for (int ma = 0; ma < 2; ++ma)
                #pragma unroll
                for (int j = 0; j < 8; ++j)
                    mma16816(acc[ma][j], Af[ma][0], Af[ma][1], Af[ma][2], Af[ma][3],
                             Bf[j >> 1][(j & 1) * 2], Bf[j >> 1][(j & 1) * 2 + 1]);
        }
        __syncthreads();
    }

    // ---- epilogue (validated mapping) ----
    #pragma unroll
    for (int ma = 0; ma < 2; ++ma) {
        float rs0 = 0.0f, rs1 = 0.0f;
        #pragma unroll
        for (int j = 0; j < 8; ++j) {
            int col = n_base + j * 8 + (lane & 3) * 2;
            float h0 = hp_s[col], h1 = hp_s[col + 1];
            float w0 = wv_s[col], w1 = wv_s[col + 1];
            rs0 = fmaf(tanhf(acc[ma][j][0] + h0), w0, rs0);
            rs0 = fmaf(tanhf(acc[ma][j][1] + h1), w1, rs0);
            rs1 = fmaf(tanhf(acc[ma][j][2] + h0), w0, rs1);
            rs1 = fmaf(tanhf(acc[ma][j][3] + h1), w1, rs1);
        }
        #pragma unroll
        for (int off = 1; off <= 2; off <<= 1) {
            rs0 += __shfl_xor_sync(0xffffffffu, rs0, off);
            rs1 += __shfl_xor_sync(0xffffffffu, rs1, off);
        }
        if ((lane & 3) == 0) {
            int r0 = m_base + ma * 16 + (lane >> 2);
            red[r0 * 2 + (wid & 1)] = rs0;
            red[(r0 + 8) * 2 + (wid & 1)] = rs1;
        }
    }
    __syncthreads();
    if (tid < 128)
        g_partial[(size_t)ntile * M_ + mtile * 128 + tid] = red[tid * 2] + red[tid * 2 + 1];
}

// ---------------------------------------------------------------------------
// softmax: fold 4 n-tile partials, softmax over S, write g_scores. grid=B_.
// ---------------------------------------------------------------------------
__global__ __launch_bounds__(512) void softmax_kernel() {
    __shared__ float sc_s[S_];
    __shared__ float red2[512];
    const int b = blockIdx.x, tid = threadIdx.x;

    float lmax = -1e30f;
    for (int s = tid; s < S_; s += 512) {
        size_t m = (size_t)b * S_ + s;
        float v = g_partial[m] + g_partial[M_ + m] +
                  g_partial[2 * (size_t)M_ + m] + g_partial[3 * (size_t)M_ + m];
        sc_s[s] = v;
        lmax = fmaxf(lmax, v);
    }
    red2[tid] = lmax; __syncthreads();
    for (int off = 256; off >= 1; off >>= 1) {
        if (tid < off) red2[tid] = fmaxf(red2[tid], red2[tid + off]);
        __syncthreads();
    }
    const float mx = red2[0];
    __syncthreads();
    float lsum = 0.0f;
    for (int s = tid; s < S_; s += 512) {
        float e = __expf(sc_s[s] - mx);
        sc_s[s] = e;
        lsum += e;
    }
    red2[tid] = lsum; __syncthreads();
    for (int off = 256; off >= 1; off >>= 1) {
        if (tid < off) red2[tid] += red2[tid + off];
        __syncthreads();
    }
    const float inv = 1.0f / red2[0];
    __syncthreads();
    for (int s = tid; s < S_; s += 512)
        g_scores[b * S_ + s] = sc_s[s] * inv;
}

// ---------------------------------------------------------------------------
// context partials: uint4 (8-half) per thread per step.
// grid (B_, 4 dc-blocks of 256 cols, 8 schunks), 256 threads.
// ---------------------------------------------------------------------------
__global__ __launch_bounds__(256) void context_kernel()
{
    __shared__ float attn_s[512];
    __shared__ float redc[8][256];

    const int b = blockIdx.x, dc = blockIdx.y, sc = blockIdx.z, tid = threadIdx.x;
    const int s0 = sc * 512;

    for (int s = tid; s < 512; s += 256)
        attn_s[s] = g_scores[b * S_ + s0 + s];
    __syncthreads();

    const int tsub = tid >> 5, lane = tid & 31;
    const __half* base = (const __half*)g_enc16
                       + ((size_t)b * S_ + s0) * D2_ + dc * 256 + lane * 8;
    float acc[8];
    #pragma unroll
    for (int i = 0; i < 8; ++i) acc[i] = 0.0f;

    #pragma unroll 4
    for (int s = tsub; s < 512; s += 8) {
        float a = attn_s[s];
        uint4 raw = *(const uint4*)(base + (size_t)s * D2_);
        float2 e0 = __half22float2(*(__half2*)&raw.x);
        float2 e1 = __half22float2(*(__half2*)&raw.y);
        float2 e2 = __half22float2(*(__half2*)&raw.z);
        float2 e3 = __half22float2(*(__half2*)&raw.w);
        acc[0] = fmaf(a, e0.x, acc[0]);
        acc[1] = fmaf(a, e0.y, acc[1]);
        acc[2] = fmaf(a, e1.x, acc[2]);
        acc[3] = fmaf(a, e1.y, acc[3]);
        acc[4] = fmaf(a, e2.x, acc[4]);
        acc[5] = fmaf(a, e2.y, acc[5]);
        acc[6] = fmaf(a, e3.x, acc[6]);
        acc[7] = fmaf(a, e3.y, acc[7]);
    }
    #pragma unroll
    for (int i = 0; i < 8; ++i) redc[tsub][lane * 8 + i] = acc[i];
    __syncthreads();

    {
        float s = 0.0f;
        #pragma unroll
        for (int t = 0; t < 8; ++t) s += redc[t][tid];
        g_ctx[((size_t)sc * B_ + b) * D2_ + dc * 256 + tid] = s;
    }
}

// ---------------------------------------------------------------------------
// reduce 8 context partials -> out
// ---------------------------------------------------------------------------
__global__ __launch_bounds__(256) void ctx_reduce_kernel(float* __restrict__ out) {
    int i = blockIdx.x * 256 + threadIdx.x;
    float s = 0.0f;
    #pragma unroll
    for (int p = 0; p < 8; ++p) s += g_ctx[(size_t)p * B_ * D2_ + i];
    out[i] = s;
}

// ---------------------------------------------------------------------------
// Launch
// ---------------------------------------------------------------------------
extern "C" void kernel_launch(void* const* d_in, const int* in_sizes, int n_in,
                              void* d_out, int out_size) {
    const float* hidden = (const float*)d_in[0];
    const float* enc    = (const float*)d_in[1];
    const float* W      = (const float*)d_in[2];
    const float* b_attn = (const float*)d_in[3];
    const float* wv     = (const float*)d_in[4];
    float* out = (float*)d_out;

    static int smem_set = 0;
    if (!smem_set) {
        cudaFuncSetAttribute(scores_kernel,
                             cudaFuncAttributeMaxDynamicSharedMemorySize, SMEM_DYN);
        smem_set = 1;
    }

    hproj_kernel<<<B_, 512>>>(hidden, W, b_attn);
    wpack_kernel<<<(D2_ * H_) / 256, 256>>>(W);
    epack_kernel<<<(unsigned)(((size_t)M_ * D2_ / 32) / 256), 256>>>(enc);
    scores_kernel<<<(M_ / 128) * 4, 256, SMEM_DYN>>>(wv);
    softmax_kernel<<<B_, 512>>>();
    context_kernel<<<dim3(B_, 4, 8), 256>>>();
    ctx_reduce_kernel<<<(B_ * D2_) / 256, 256>>>(out);
}

// round 15
// speedup vs baseline: 1.1806x; 1.1018x over previous
#include <cuda_runtime.h>
#include <cuda_fp16.h>
#include <math.h>
#include <stdint.h>

// Problem sizes (fixed)
#define B_    16
#define S_    4096
#define D2_   1024      // 2H
#define H_    512
#define M_    (B_ * S_)

// Scratch
__device__ float g_hproj[B_ * H_];
__device__ float g_partial[4 * M_];          // per-ntile partial row sums
__device__ float g_scores[M_];               // softmaxed attention
__device__ float g_ctx[16 * B_ * D2_];       // per-schunk context partials
__device__ __half g_W16[D2_ * H_];           // W bottom fp16 [k][n]
__device__ uint4  g_enc16[(size_t)M_ * D2_ / 8];   // enc fp16, row-major [M][1024]

// smem pitches (halves) — R9 configuration
#define PA 40     // A rows: 32 halves + 8 pad (80 B)
#define PB 136    // B rows: 128 halves + 8 pad (272 B)
#define STAGES 4
#define ASZ (128 * PA)          // 5120 halves
#define BSZ (32 * PB)           // 4352 halves
#define STAGE_BYTES ((ASZ + BSZ) * 2)        // 18944
#define SMEM_DYN (STAGES * STAGE_BYTES)      // 75776

// ---------------------------------------------------------------------------
// helpers
// ---------------------------------------------------------------------------
__device__ __forceinline__ uint32_t smem_u32(const void* p) {
    uint32_t a;
    asm("{ .reg .u64 t; cvta.to.shared.u64 t, %1; cvt.u32.u64 %0, t; }" : "=r"(a) : "l"(p));
    return a;
}
__device__ __forceinline__ void ldmx4(uint32_t addr, uint32_t& r0, uint32_t& r1,
                                      uint32_t& r2, uint32_t& r3) {
    asm volatile("ldmatrix.sync.aligned.m8n8.x4.shared.b16 {%0,%1,%2,%3}, [%4];"
                 : "=r"(r0), "=r"(r1), "=r"(r2), "=r"(r3) : "r"(addr));
}
__device__ __forceinline__ void ldmx4t(uint32_t addr, uint32_t& r0, uint32_t& r1,
                                       uint32_t& r2, uint32_t& r3) {
    asm volatile("ldmatrix.sync.aligned.m8n8.x4.trans.shared.b16 {%0,%1,%2,%3}, [%4];"
                 : "=r"(r0), "=r"(r1), "=r"(r2), "=r"(r3) : "r"(addr));
}
__device__ __forceinline__ void mma16816(float* c, uint32_t a0, uint32_t a1,
                                         uint32_t a2, uint32_t a3,
                                         uint32_t b0, uint32_t b1) {
    asm volatile(
        "mma.sync.aligned.m16n8k16.row.col.f32.f16.f16.f32 "
        "{%0,%1,%2,%3},{%4,%5,%6,%7},{%8,%9},{%0,%1,%2,%3};"
        : "+f"(c[0]), "+f"(c[1]), "+f"(c[2]), "+f"(c[3])
        : "r"(a0), "r"(a1), "r"(a2), "r"(a3), "r"(b0), "r"(b1));
}
__device__ __forceinline__ void cp16(uint32_t dst, const void* src) {
    asm volatile("cp.async.cg.shared.global [%0], [%1], 16;" :: "r"(dst), "l"(src));
}

// ---------------------------------------------------------------------------
// hproj[b][h] = b_attn[h] + hidden[b] @ W_top[:,h]
// ---------------------------------------------------------------------------
__global__ __launch_bounds__(512) void hproj_kernel(
    const float* __restrict__ hidden, const float* __restrict__ W,
    const float* __restrict__ b_attn)
{
    __shared__ float hid_s[D2_];
    int b = blockIdx.x, h = threadIdx.x;
    for (int d = threadIdx.x; d < D2_; d += blockDim.x)
        hid_s[d] = hidden[b * D2_ + d];
    __syncthreads();
    float acc = b_attn[h];
    #pragma unroll 8
    for (int d = 0; d < D2_; ++d)
        acc = fmaf(hid_s[d], W[(size_t)d * H_ + h], acc);
    g_hproj[b * H_ + h] = acc;
}

// ---------------------------------------------------------------------------
// pack W bottom [1024,512] fp32 -> fp16 [k][n]
// ---------------------------------------------------------------------------
__global__ __launch_bounds__(256) void wpack_kernel(const float* __restrict__ W) {
    int idx = blockIdx.x * 256 + threadIdx.x;
    g_W16[idx] = __float2half(W[(size_t)D2_ * H_ + idx]);
}

// ---------------------------------------------------------------------------
// pack enc [M,1024] fp32 -> fp16 (8 elems / thread, coalesced — R9 version)
// ---------------------------------------------------------------------------
__global__ __launch_bounds__(256) void epack_kernel(const float* __restrict__ enc) {
    size_t idx = (size_t)blockIdx.x * 256 + threadIdx.x;   // 0 .. 8M-1
    const float4* src = (const float4*)enc + idx * 2;
    float4 f0 = src[0], f1 = src[1];
    __half2 h0 = __floats2half2_rn(f0.x, f0.y);
    __half2 h1 = __floats2half2_rn(f0.z, f0.w);
    __half2 h2 = __floats2half2_rn(f1.x, f1.y);
    __half2 h3 = __floats2half2_rn(f1.z, f1.w);
    uint4 o;
    o.x = *(uint32_t*)&h0; o.y = *(uint32_t*)&h1;
    o.z = *(uint32_t*)&h2; o.w = *(uint32_t*)&h3;
    g_enc16[idx] = o;
}

// ---------------------------------------------------------------------------
// scores GEMM — R9 winner minus the redundant bottom barrier.
// CTA 128x128x32, 4-stage cp.async, 2 CTAs/SM.
// ---------------------------------------------------------------------------
__global__ __launch_bounds__(256, 2) void scores_kernel(const float* __restrict__ wv)
{
    extern __shared__ __align__(16) char dsm[];
    __shared__ float hp_s[128], wv_s[128], red[256];

    const int tid = threadIdx.x, wid = tid >> 5, lane = tid & 31;
    const int mtile = blockIdx.x >> 2;     // ntile-fastest for L2 A reuse
    const int ntile = blockIdx.x & 3;
    const int b = mtile >> 5;

    if (tid < 128) {
        hp_s[tid] = g_hproj[b * H_ + ntile * 128 + tid];
        wv_s[tid] = wv[ntile * 128 + tid];
    }

    const __half* Aenc = (const __half*)g_enc16 + (size_t)mtile * 128 * D2_;
    const __half* Bw   = g_W16 + ntile * 128;
    const uint32_t sm_b = smem_u32(dsm);

    const int ac0 = tid * 2;
    auto issue_stage = [&](int kc, int s) {
        uint32_t base = sm_b + (uint32_t)s * STAGE_BYTES;
        #pragma unroll
        for (int i = 0; i < 2; ++i) {
            int c = ac0 + i;
            int row = c >> 2, cc = c & 3;
            cp16(base + (uint32_t)(row * PA * 2 + cc * 16),
                 Aenc + (size_t)row * D2_ + kc * 32 + cc * 8);
        }
        uint32_t bbase = base + ASZ * 2;
        #pragma unroll
        for (int i = 0; i < 2; ++i) {
            int c = ac0 + i;
            int row = c >> 4, cc = c & 15;
            cp16(bbase + (uint32_t)(row * PB * 2 + cc * 16),
                 Bw + (size_t)(kc * 32 + row) * H_ + cc * 8);
        }
        asm volatile("cp.async.commit_group;" ::: "memory");
    };

    float acc[2][8][4];
    #pragma unroll
    for (int i = 0; i < 2; ++i)
        #pragma unroll
        for (int j = 0; j < 8; ++j)
            #pragma unroll
            for (int t = 0; t < 4; ++t) acc[i][j][t] = 0.0f;

    const int m_base = (wid >> 1) * 32;
    const int n_base = (wid & 1) * 64;
    const uint32_t a_off = ((m_base + (lane & 15)) * PA + (lane >> 4) * 8) * 2;
    const uint32_t b_off = (((lane & 7) + ((lane >> 3) & 1) * 8) * PB
                            + n_base + (lane >> 4) * 8) * 2;

    issue_stage(0, 0);
    issue_stage(1, 1);
    issue_stage(2, 2);

    for (int kc = 0; kc < 32; ++kc) {
        asm volatile("cp.async.wait_group 2;" ::: "memory");
        __syncthreads();
        if (kc + 3 < 32) issue_stage(kc + 3, (kc + 3) & (STAGES - 1));

        const uint32_t sbase = sm_b + (uint32_t)(kc & (STAGES - 1)) * STAGE_BYTES;
        const uint32_t a_base = sbase + a_off;
        const uint32_t b_base = sbase + ASZ * 2 + b_off;
        #pragma unroll
        for (int ks = 0; ks < 2; ++ks) {
            uint32_t Af[2][4], Bf[4][4];
            #pragma unroll
            for (int ma = 0; ma < 2; ++ma)
                ldmx4(a_base + (ma * 16 * PA + ks * 16) * 2,
                      Af[ma][0], Af[ma][1], Af[ma][2], Af[ma][3]);
            #pragma unroll
            for (int g = 0; g < 4; ++g)
                ldmx4t(b_base + (ks * 16 * PB + g * 16) * 2,
                       Bf[g][0], Bf[g][1], Bf[g][2], Bf[g][3]);
            #pragma unroll
            for (int ma = 0; ma < 2; ++ma)
                #pragma unroll
                for (int j = 0; j < 8; ++j)
                    mma16816(acc[ma][j], Af[ma][0], Af[ma][1], Af[ma][2], Af[ma][3],
                             Bf[j >> 1][(j & 1) * 2], Bf[j >> 1][(j & 1) * 2 + 1]);
        }
        // bottom barrier removed: iter kc+1's top __syncthreads orders
        // compute(kc) before issue_stage(kc+4) — the first reuse of stage kc&3.
    }

    // ---- epilogue (validated mapping) ----
    #pragma unroll
    for (int ma = 0; ma < 2; ++ma) {
        float rs0 = 0.0f, rs1 = 0.0f;
        #pragma unroll
        for (int j = 0; j < 8; ++j) {
            int col = n_base + j * 8 + (lane & 3) * 2;
            float h0 = hp_s[col], h1 = hp_s[col + 1];
            float w0 = wv_s[col], w1 = wv_s[col + 1];
            rs0 = fmaf(tanhf(acc[ma][j][0] + h0), w0, rs0);
            rs0 = fmaf(tanhf(acc[ma][j][1] + h1), w1, rs0);
            rs1 = fmaf(tanhf(acc[ma][j][2] + h0), w0, rs1);
            rs1 = fmaf(tanhf(acc[ma][j][3] + h1), w1, rs1);
        }
        #pragma unroll
        for (int off = 1; off <= 2; off <<= 1) {
            rs0 += __shfl_xor_sync(0xffffffffu, rs0, off);
            rs1 += __shfl_xor_sync(0xffffffffu, rs1, off);
        }
        if ((lane & 3) == 0) {
            int r0 = m_base + ma * 16 + (lane >> 2);
            red[r0 * 2 + (wid & 1)] = rs0;
            red[(r0 + 8) * 2 + (wid & 1)] = rs1;
        }
    }
    __syncthreads();
    if (tid < 128)
        g_partial[(size_t)ntile * M_ + mtile * 128 + tid] = red[tid * 2] + red[tid * 2 + 1];
}

// ---------------------------------------------------------------------------
// softmax: fold 4 n-tile partials, softmax over S, write g_scores. grid=B_.
// ---------------------------------------------------------------------------
__global__ __launch_bounds__(512) void softmax_kernel() {
    __shared__ float sc_s[S_];
    __shared__ float red2[512];
    const int b = blockIdx.x, tid = threadIdx.x;

    float lmax = -1e30f;
    for (int s = tid; s < S_; s += 512) {
        size_t m = (size_t)b * S_ + s;
        float v = g_partial[m] + g_partial[M_ + m] +
                  g_partial[2 * (size_t)M_ + m] + g_partial[3 * (size_t)M_ + m];
        sc_s[s] = v;
        lmax = fmaxf(lmax, v);
    }
    red2[tid] = lmax; __syncthreads();
    for (int off = 256; off >= 1; off >>= 1) {
        if (tid < off) red2[tid] = fmaxf(red2[tid], red2[tid + off]);
        __syncthreads();
    }
    const float mx = red2[0];
    __syncthreads();
    float lsum = 0.0f;
    for (int s = tid; s < S_; s += 512) {
        float e = __expf(sc_s[s] - mx);
        sc_s[s] = e;
        lsum += e;
    }
    red2[tid] = lsum; __syncthreads();
    for (int off = 256; off >= 1; off >>= 1) {
        if (tid < off) red2[tid] += red2[tid + off];
        __syncthreads();
    }
    const float inv = 1.0f / red2[0];
    __syncthreads();
    for (int s = tid; s < S_; s += 512)
        g_scores[b * S_ + s] = sc_s[s] * inv;
}

// ---------------------------------------------------------------------------
// context partials: uint4 (8-half) per thread per step, 1024 CTAs.
// grid (B_, 4 dc-blocks of 256 cols, 16 schunks of 256), 256 threads.
// ---------------------------------------------------------------------------
__global__ __launch_bounds__(256) void context_kernel()
{
    __shared__ float attn_s[256];
    __shared__ float redc[8][256];

    const int b = blockIdx.x, dc = blockIdx.y, sc = blockIdx.z, tid = threadIdx.x;
    const int s0 = sc * 256;

    if (tid < 256)
        attn_s[tid] = g_scores[b * S_ + s0 + tid];
    __syncthreads();

    const int tsub = tid >> 5, lane = tid & 31;
    const __half* base = (const __half*)g_enc16
                       + ((size_t)b * S_ + s0) * D2_ + dc * 256 + lane * 8;
    float acc[8];
    #pragma unroll
    for (int i = 0; i < 8; ++i) acc[i] = 0.0f;

    #pragma unroll 4
    for (int s = tsub; s < 256; s += 8) {
        float a = attn_s[s];
        uint4 raw = *(const uint4*)(base + (size_t)s * D2_);
        float2 e0 = __half22float2(*(__half2*)&raw.x);
        float2 e1 = __half22float2(*(__half2*)&raw.y);
        float2 e2 = __half22float2(*(__half2*)&raw.z);
        float2 e3 = __half22float2(*(__half2*)&raw.w);
        acc[0] = fmaf(a, e0.x, acc[0]);
        acc[1] = fmaf(a, e0.y, acc[1]);
        acc[2] = fmaf(a, e1.x, acc[2]);
        acc[3] = fmaf(a, e1.y, acc[3]);
        acc[4] = fmaf(a, e2.x, acc[4]);
        acc[5] = fmaf(a, e2.y, acc[5]);
        acc[6] = fmaf(a, e3.x, acc[6]);
        acc[7] = fmaf(a, e3.y, acc[7]);
    }
    #pragma unroll
    for (int i = 0; i < 8; ++i) redc[tsub][lane * 8 + i] = acc[i];
    __syncthreads();

    {
        float s = 0.0f;
        #pragma unroll
        for (int t = 0; t < 8; ++t) s += redc[t][tid];
        g_ctx[((size_t)sc * B_ + b) * D2_ + dc * 256 + tid] = s;
    }
}

// ---------------------------------------------------------------------------
// reduce 16 context partials -> out
// ---------------------------------------------------------------------------
__global__ __launch_bounds__(256) void ctx_reduce_kernel(float* __restrict__ out) {
    int i = blockIdx.x * 256 + threadIdx.x;
    float s = 0.0f;
    #pragma unroll
    for (int p = 0; p < 16; ++p) s += g_ctx[(size_t)p * B_ * D2_ + i];
    out[i] = s;
}

// ---------------------------------------------------------------------------
// Launch
// ---------------------------------------------------------------------------
extern "C" void kernel_launch(void* const* d_in, const int* in_sizes, int n_in,
                              void* d_out, int out_size) {
    const float* hidden = (const float*)d_in[0];
    const float* enc    = (const float*)d_in[1];
    const float* W      = (const float*)d_in[2];
    const float* b_attn = (const float*)d_in[3];
    const float* wv     = (const float*)d_in[4];
    float* out = (float*)d_out;

    static int smem_set = 0;
    if (!smem_set) {
        cudaFuncSetAttribute(scores_kernel,
                             cudaFuncAttributeMaxDynamicSharedMemorySize, SMEM_DYN);
        smem_set = 1;
    }

    hproj_kernel<<<B_, 512>>>(hidden, W, b_attn);
    wpack_kernel<<<(D2_ * H_) / 256, 256>>>(W);
    epack_kernel<<<(unsigned)(((size_t)M_ * D2_ / 8) / 256), 256>>>(enc);
    scores_kernel<<<(M_ / 128) * 4, 256, SMEM_DYN>>>(wv);
    softmax_kernel<<<B_, 512>>>();
    context_kernel<<<dim3(B_, 4, 16), 256>>>();
    ctx_reduce_kernel<<<(B_ * D2_) / 256, 256>>>(out);
}

// round 17
// speedup vs baseline: 1.1980x; 1.0148x over previous
#include <cuda_runtime.h>
#include <cuda_fp16.h>
#include <math.h>
#include <stdint.h>

// Problem sizes (fixed)
#define B_    16
#define S_    4096
#define D2_   1024      // 2H
#define H_    512
#define M_    (B_ * S_)

// Scratch
__device__ float g_hproj[B_ * H_];
__device__ float g_partial[4 * M_];          // per-ntile partial row sums
__device__ float g_scores[M_];               // softmaxed attention
__device__ float g_ctx[16 * B_ * D2_];       // per-schunk context partials
__device__ __half g_W16[D2_ * H_];           // W bottom fp16 [k][n]
__device__ uint4  g_enc16[(size_t)M_ * D2_ / 8];   // enc fp16, row-major [M][1024]

// smem pitches (halves) — R9/R15 configuration
#define PA 40     // A rows: 32 halves + 8 pad (80 B)
#define PB 136    // B rows: 128 halves + 8 pad (272 B)
#define STAGES 4
#define ASZ (128 * PA)          // 5120 halves
#define BSZ (32 * PB)           // 4352 halves
#define STAGE_BYTES ((ASZ + BSZ) * 2)        // 18944
#define SMEM_DYN (STAGES * STAGE_BYTES)      // 75776

// ---------------------------------------------------------------------------
// helpers
// ---------------------------------------------------------------------------
__device__ __forceinline__ uint32_t smem_u32(const void* p) {
    uint32_t a;
    asm("{ .reg .u64 t; cvta.to.shared.u64 t, %1; cvt.u32.u64 %0, t; }" : "=r"(a) : "l"(p));
    return a;
}
__device__ __forceinline__ void ldmx4(uint32_t addr, uint32_t& r0, uint32_t& r1,
                                      uint32_t& r2, uint32_t& r3) {
    asm volatile("ldmatrix.sync.aligned.m8n8.x4.shared.b16 {%0,%1,%2,%3}, [%4];"
                 : "=r"(r0), "=r"(r1), "=r"(r2), "=r"(r3) : "r"(addr));
}
__device__ __forceinline__ void ldmx4t(uint32_t addr, uint32_t& r0, uint32_t& r1,
                                       uint32_t& r2, uint32_t& r3) {
    asm volatile("ldmatrix.sync.aligned.m8n8.x4.trans.shared.b16 {%0,%1,%2,%3}, [%4];"
                 : "=r"(r0), "=r"(r1), "=r"(r2), "=r"(r3) : "r"(addr));
}
__device__ __forceinline__ void mma16816(float* c, uint32_t a0, uint32_t a1,
                                         uint32_t a2, uint32_t a3,
                                         uint32_t b0, uint32_t b1) {
    asm volatile(
        "mma.sync.aligned.m16n8k16.row.col.f32.f16.f16.f32 "
        "{%0,%1,%2,%3},{%4,%5,%6,%7},{%8,%9},{%0,%1,%2,%3};"
        : "+f"(c[0]), "+f"(c[1]), "+f"(c[2]), "+f"(c[3])
        : "r"(a0), "r"(a1), "r"(a2), "r"(a3), "r"(b0), "r"(b1));
}
__device__ __forceinline__ void cp16(uint32_t dst, const void* src) {
    asm volatile("cp.async.cg.shared.global [%0], [%1], 16;" :: "r"(dst), "l"(src));
}

// ---------------------------------------------------------------------------
// hproj[b][h] = b_attn[h] + hidden[b] @ W_top[:,h]
// ---------------------------------------------------------------------------
__global__ __launch_bounds__(512) void hproj_kernel(
    const float* __restrict__ hidden, const float* __restrict__ W,
    const float* __restrict__ b_attn)
{
    __shared__ float hid_s[D2_];
    int b = blockIdx.x, h = threadIdx.x;
    for (int d = threadIdx.x; d < D2_; d += blockDim.x)
        hid_s[d] = hidden[b * D2_ + d];
    __syncthreads();
    float acc = b_attn[h];
    #pragma unroll 8
    for (int d = 0; d < D2_; ++d)
        acc = fmaf(hid_s[d], W[(size_t)d * H_ + h], acc);
    g_hproj[b * H_ + h] = acc;
}

// ---------------------------------------------------------------------------
// pack W bottom [1024,512] fp32 -> fp16 [k][n]
// ---------------------------------------------------------------------------
__global__ __launch_bounds__(256) void wpack_kernel(const float* __restrict__ W) {
    int idx = blockIdx.x * 256 + threadIdx.x;
    g_W16[idx] = __float2half(W[(size_t)D2_ * H_ + idx]);
}

// ---------------------------------------------------------------------------
// pack enc [M,1024] fp32 -> fp16: 2 block-strided uint4 per thread
// (coalesced; 2x MLP; half the CTAs of R15)
// ---------------------------------------------------------------------------
__global__ __launch_bounds__(256) void epack_kernel(const float* __restrict__ enc) {
    size_t idx0 = (size_t)blockIdx.x * 512 + threadIdx.x;
    const float4* s0 = (const float4*)enc + idx0 * 2;
    const float4* s1 = (const float4*)enc + (idx0 + 256) * 2;
    float4 f0 = s0[0], f1 = s0[1], f2 = s1[0], f3 = s1[1];

    __half2 a0 = __floats2half2_rn(f0.x, f0.y);
    __half2 a1 = __floats2half2_rn(f0.z, f0.w);
    __half2 a2 = __floats2half2_rn(f1.x, f1.y);
    __half2 a3 = __floats2half2_rn(f1.z, f1.w);
    uint4 o0;
    o0.x = *(uint32_t*)&a0; o0.y = *(uint32_t*)&a1;
    o0.z = *(uint32_t*)&a2; o0.w = *(uint32_t*)&a3;
    g_enc16[idx0] = o0;

    __half2 b0 = __floats2half2_rn(f2.x, f2.y);
    __half2 b1 = __floats2half2_rn(f2.z, f2.w);
    __half2 b2 = __floats2half2_rn(f3.x, f3.y);
    __half2 b3 = __floats2half2_rn(f3.z, f3.w);
    uint4 o1;
    o1.x = *(uint32_t*)&b0; o1.y = *(uint32_t*)&b1;
    o1.z = *(uint32_t*)&b2; o1.w = *(uint32_t*)&b3;
    g_enc16[idx0 + 256] = o1;
}

// ---------------------------------------------------------------------------
// scores GEMM — R15 winner (byte-identical): CTA 128x128x32, 4-stage
// cp.async, 2 CTAs/SM, single barrier per kc.
// ---------------------------------------------------------------------------
__global__ __launch_bounds__(256, 2) void scores_kernel(const float* __restrict__ wv)
{
    extern __shared__ __align__(16) char dsm[];
    __shared__ float hp_s[128], wv_s[128], red[256];

    const int tid = threadIdx.x, wid = tid >> 5, lane = tid & 31;
    const int mtile = blockIdx.x >> 2;     // ntile-fastest for L2 A reuse
    const int ntile = blockIdx.x & 3;
    const int b = mtile >> 5;

    if (tid < 128) {
        hp_s[tid] = g_hproj[b * H_ + ntile * 128 + tid];
        wv_s[tid] = wv[ntile * 128 + tid];
    }

    const __half* Aenc = (const __half*)g_enc16 + (size_t)mtile * 128 * D2_;
    const __half* Bw   = g_W16 + ntile * 128;
    const uint32_t sm_b = smem_u32(dsm);

    const int ac0 = tid * 2;
    auto issue_stage = [&](int kc, int s) {
        uint32_t base = sm_b + (uint32_t)s * STAGE_BYTES;
        #pragma unroll
        for (int i = 0; i < 2; ++i) {
            int c = ac0 + i;
            int row = c >> 2, cc = c & 3;
            cp16(base + (uint32_t)(row * PA * 2 + cc * 16),
                 Aenc + (size_t)row * D2_ + kc * 32 + cc * 8);
        }
        uint32_t bbase = base + ASZ * 2;
        #pragma unroll
        for (int i = 0; i < 2; ++i) {
            int c = ac0 + i;
            int row = c >> 4, cc = c & 15;
            cp16(bbase + (uint32_t)(row * PB * 2 + cc * 16),
                 Bw + (size_t)(kc * 32 + row) * H_ + cc * 8);
        }
        asm volatile("cp.async.commit_group;" ::: "memory");
    };

    float acc[2][8][4];
    #pragma unroll
    for (int i = 0; i < 2; ++i)
        #pragma unroll
        for (int j = 0; j < 8; ++j)
            #pragma unroll
            for (int t = 0; t < 4; ++t) acc[i][j][t] = 0.0f;

    const int m_base = (wid >> 1) * 32;
    const int n_base = (wid & 1) * 64;
    const uint32_t a_off = ((m_base + (lane & 15)) * PA + (lane >> 4) * 8) * 2;
    const uint32_t b_off = (((lane & 7) + ((lane >> 3) & 1) * 8) * PB
                            + n_base + (lane >> 4) * 8) * 2;

    issue_stage(0, 0);
    issue_stage(1, 1);
    issue_stage(2, 2);

    for (int kc = 0; kc < 32; ++kc) {
        asm volatile("cp.async.wait_group 2;" ::: "memory");
        __syncthreads();
        if (kc + 3 < 32) issue_stage(kc + 3, (kc + 3) & (STAGES - 1));

        const uint32_t sbase = sm_b + (uint32_t)(kc & (STAGES - 1)) * STAGE_BYTES;
        const uint32_t a_base = sbase + a_off;
        const uint32_t b_base = sbase + ASZ * 2 + b_off;
        #pragma unroll
        for (int ks = 0; ks < 2; ++ks) {
            uint32_t Af[2][4], Bf[4][4];
            #pragma unroll
            for (int ma = 0; ma < 2; ++ma)
                ldmx4(a_base + (ma * 16 * PA + ks * 16) * 2,
                      Af[ma][0], Af[ma][1], Af[ma][2], Af[ma][3]);
            #pragma unroll
            for (int g = 0; g < 4; ++g)
                ldmx4t(b_base + (ks * 16 * PB + g * 16) * 2,
                       Bf[g][0], Bf[g][1], Bf[g][2], Bf[g][3]);
            #pragma unroll
            for (int ma = 0; ma < 2; ++ma)
                #pragma unroll
                for (int j = 0; j < 8; ++j)
                    mma16816(acc[ma][j], Af[ma][0], Af[ma][1], Af[ma][2], Af[ma][3],
                             Bf[j >> 1][(j & 1) * 2], Bf[j >> 1][(j & 1) * 2 + 1]);
        }
        // bottom barrier removed: iter kc+1's top __syncthreads orders
        // compute(kc) before issue_stage(kc+4) — the first reuse of stage kc&3.
    }

    // ---- epilogue (validated mapping) ----
    #pragma unroll
    for (int ma = 0; ma < 2; ++ma) {
        float rs0 = 0.0f, rs1 = 0.0f;
        #pragma unroll
        for (int j = 0; j < 8; ++j) {
            int col = n_base + j * 8 + (lane & 3) * 2;
            float h0 = hp_s[col], h1 = hp_s[col + 1];
            float w0 = wv_s[col], w1 = wv_s[col + 1];
            rs0 = fmaf(tanhf(acc[ma][j][0] + h0), w0, rs0);
            rs0 = fmaf(tanhf(acc[ma][j][1] + h1), w1, rs0);
            rs1 = fmaf(tanhf(acc[ma][j][2] + h0), w0, rs1);
            rs1 = fmaf(tanhf(acc[ma][j][3] + h1), w1, rs1);
        }
        #pragma unroll
        for (int off = 1; off <= 2; off <<= 1) {
            rs0 += __shfl_xor_sync(0xffffffffu, rs0, off);
            rs1 += __shfl_xor_sync(0xffffffffu, rs1, off);
        }
        if ((lane & 3) == 0) {
            int r0 = m_base + ma * 16 + (lane >> 2);
            red[r0 * 2 + (wid & 1)] = rs0;
            red[(r0 + 8) * 2 + (wid & 1)] = rs1;
        }
    }
    __syncthreads();
    if (tid < 128)
        g_partial[(size_t)ntile * M_ + mtile * 128 + tid] = red[tid * 2] + red[tid * 2 + 1];
}

// ---------------------------------------------------------------------------
// softmax: float4 fold of the 4 n-tile partial planes, softmax over S.
// grid=B_, 512 threads, 2 float4 groups per thread.
// ---------------------------------------------------------------------------
__global__ __launch_bounds__(512) void softmax_kernel() {
    __shared__ float4 sc4[S_ / 4];        // 1024 float4 = 16 KB
    __shared__ float red2[512];
    const int b = blockIdx.x, tid = threadIdx.x;
    const float4* pl = (const float4*)g_partial + (size_t)b * (S_ / 4);
    const size_t PSTR = (size_t)M_ / 4;   // plane stride in float4

    float lmax = -1e30f;
    #pragma unroll
    for (int g = 0; g < 2; ++g) {
        int f = tid + g * 512;
        float4 v0 = pl[f];
        float4 v1 = pl[PSTR + f];
        float4 v2 = pl[2 * PSTR + f];
        float4 v3 = pl[3 * PSTR + f];
        float4 v;
        v.x = v0.x + v1.x + v2.x + v3.x;
        v.y = v0.y + v1.y + v2.y + v3.y;
        v.z = v0.z + v1.z + v2.z + v3.z;
        v.w = v0.w + v1.w + v2.w + v3.w;
        sc4[f] = v;
        lmax = fmaxf(lmax, fmaxf(fmaxf(v.x, v.y), fmaxf(v.z, v.w)));
    }
    red2[tid] = lmax; __syncthreads();
    for (int off = 256; off >= 1; off >>= 1) {
        if (tid < off) red2[tid] = fmaxf(red2[tid], red2[tid + off]);
        __syncthreads();
    }
    const float mx = red2[0];
    __syncthreads();

    float lsum = 0.0f;
    #pragma unroll
    for (int g = 0; g < 2; ++g) {
        int f = tid + g * 512;
        float4 v = sc4[f];
        v.x = __expf(v.x - mx); v.y = __expf(v.y - mx);
        v.z = __expf(v.z - mx); v.w = __expf(v.w - mx);
        sc4[f] = v;
        lsum += v.x + v.y + v.z + v.w;
    }
    red2[tid] = lsum; __syncthreads();
    for (int off = 256; off >= 1; off >>= 1) {
        if (tid < off) red2[tid] += red2[tid + off];
        __syncthreads();
    }
    const float inv = 1.0f / red2[0];
    __syncthreads();

    float4* outp = (float4*)g_scores + (size_t)b * (S_ / 4);
    #pragma unroll
    for (int g = 0; g < 2; ++g) {
        int f = tid + g * 512;
        float4 v = sc4[f];
        v.x *= inv; v.y *= inv; v.z *= inv; v.w *= inv;
        outp[f] = v;
    }
}

// ---------------------------------------------------------------------------
// context partials: uint4 (8-half) per thread per step, 1024 CTAs (R15).
// grid (B_, 4 dc-blocks of 256 cols, 16 schunks of 256), 256 threads.
// ---------------------------------------------------------------------------
__global__ __launch_bounds__(256) void context_kernel()
{
    __shared__ float attn_s[256];
    __shared__ float redc[8][256];

    const int b = blockIdx.x, dc = blockIdx.y, sc = blockIdx.z, tid = threadIdx.x;
    const int s0 = sc * 256;

    attn_s[tid] = g_scores[b * S_ + s0 + tid];
    __syncthreads();

    const int tsub = tid >> 5, lane = tid & 31;
    const __half* base = (const __half*)g_enc16
                       + ((size_t)b * S_ + s0) * D2_ + dc * 256 + lane * 8;
    float acc[8];
    #pragma unroll
    for (int i = 0; i < 8; ++i) acc[i] = 0.0f;

    #pragma unroll 4
    for (int s = tsub; s < 256; s += 8) {
        float a = attn_s[s];
        uint4 raw = *(const uint4*)(base + (size_t)s * D2_);
        float2 e0 = __half22float2(*(__half2*)&raw.x);
        float2 e1 = __half22float2(*(__half2*)&raw.y);
        float2 e2 = __half22float2(*(__half2*)&raw.z);
        float2 e3 = __half22float2(*(__half2*)&raw.w);
        acc[0] = fmaf(a, e0.x, acc[0]);
        acc[1] = fmaf(a, e0.y, acc[1]);
        acc[2] = fmaf(a, e1.x, acc[2]);
        acc[3] = fmaf(a, e1.y, acc[3]);
        acc[4] = fmaf(a, e2.x, acc[4]);
        acc[5] = fmaf(a, e2.y, acc[5]);
        acc[6] = fmaf(a, e3.x, acc[6]);
        acc[7] = fmaf(a, e3.y, acc[7]);
    }
    #pragma unroll
    for (int i = 0; i < 8; ++i) redc[tsub][lane * 8 + i] = acc[i];
    __syncthreads();

    {
        float s = 0.0f;
        #pragma unroll
        for (int t = 0; t < 8; ++t) s += redc[t][tid];
        g_ctx[((size_t)sc * B_ + b) * D2_ + dc * 256 + tid] = s;
    }
}

// ---------------------------------------------------------------------------
// reduce 16 context partials -> out
// ---------------------------------------------------------------------------
__global__ __launch_bounds__(256) void ctx_reduce_kernel(float* __restrict__ out) {
    int i = blockIdx.x * 256 + threadIdx.x;
    float s = 0.0f;
    #pragma unroll
    for (int p = 0; p < 16; ++p) s += g_ctx[(size_t)p * B_ * D2_ + i];
    out[i] = s;
}

// ---------------------------------------------------------------------------
// Launch (single stream — cross-stream edges are unreliable in this harness)
// ---------------------------------------------------------------------------
extern "C" void kernel_launch(void* const* d_in, const int* in_sizes, int n_in,
                              void* d_out, int out_size) {
    const float* hidden = (const float*)d_in[0];
    const float* enc    = (const float*)d_in[1];
    const float* W      = (const float*)d_in[2];
    const float* b_attn = (const float*)d_in[3];
    const float* wv     = (const float*)d_in[4];
    float* out = (float*)d_out;

    static int smem_set = 0;
    if (!smem_set) {
        cudaFuncSetAttribute(scores_kernel,
                             cudaFuncAttributeMaxDynamicSharedMemorySize, SMEM_DYN);
        smem_set = 1;
    }

    hproj_kernel<<<B_, 512>>>(hidden, W, b_attn);
    wpack_kernel<<<(D2_ * H_) / 256, 256>>>(W);
    epack_kernel<<<(unsigned)(((size_t)M_ * D2_ / 8) / 512), 256>>>(enc);
    scores_kernel<<<(M_ / 128) * 4, 256, SMEM_DYN>>>(wv);
    softmax_kernel<<<B_, 512>>>();
    context_kernel<<<dim3(B_, 4, 16), 256>>>();
    ctx_reduce_kernel<<<(B_ * D2_) / 256, 256>>>(out);
}